// round 5
// baseline (speedup 1.0000x reference)
#include <cuda_runtime.h>
#include <stdint.h>

// Problem constants (from reference_code)
#define B_DIM    16
#define C_DIM    23
#define T_DIM    120200
#define P_DIM    1000
#define PS_DIM   200
#define STRIDE_  150
#define ACTUAL_  801           // min((T-PS)/STRIDE + 1, MAX_PATCHES)

#define BC_DIM   (B_DIM * C_DIM)                 // 368
#define V4       (PS_DIM / 4)                    // 50 float4 per patch
#define PATCH_V4 (BC_DIM * P_DIM * V4)           // 18,400,000 float4 outputs
#define QUART_V4 (PATCH_V4 / 4)                  // 4,600,000
#define MASK_N   (BC_DIM * P_DIM)                // 368,000
#define TOTAL_T  (QUART_V4 + MASK_N)             // 4,968,000 threads

// Streaming (evict-first) stores: keep the 296MB write stream out of L2 so the
// read-window overlap (50/200 floats re-read by the next patch) stays resident.
__device__ __forceinline__ void stcs4(float4* p, float4 v) {
    asm volatile("st.global.cs.v4.f32 [%0], {%1,%2,%3,%4};"
                 :: "l"(p), "f"(v.x), "f"(v.y), "f"(v.z), "f"(v.w) : "memory");
}
__device__ __forceinline__ void stcs1(float* p, float v) {
    asm volatile("st.global.cs.f32 [%0], %1;" :: "l"(p), "f"(v) : "memory");
}

// Compute one float4 of the patches output for flat float4-index `o`.
__device__ __forceinline__ float4 patch_val(const float* __restrict__ x, int o) {
    int v    = o % V4;          // float4 index within patch [0,50)
    int rest = o / V4;
    int p    = rest % P_DIM;    // patch index [0,1000)
    int bc   = rest / P_DIM;    // fused (b,c) [0,368)

    if (p >= ACTUAL_) return make_float4(0.f, 0.f, 0.f, 0.f);

    // src offset = bc*120200 + 150*p + 4*v ; 16B-aligned iff p even.
    const float* src = x + (size_t)bc * T_DIM + p * STRIDE_ + v * 4;
    if ((p & 1) == 0) {
        return *reinterpret_cast<const float4*>(src);
    } else {
        float2 a = *reinterpret_cast<const float2*>(src);
        float2 b = *reinterpret_cast<const float2*>(src + 2);
        return make_float4(a.x, a.y, b.x, b.y);
    }
}

// Fused kernel, 4 independent float4s per thread (MLP=4):
//   tid < QUART_V4 : patches float4 at tid + k*QUART_V4, k = 0..3
//   else           : one mask float
__global__ void __launch_bounds__(256) to_patches_fused_kernel(
    const float* __restrict__ x, float* __restrict__ out)
{
    int tid = blockIdx.x * blockDim.x + threadIdx.x;
    if (tid >= TOTAL_T) return;

    if (tid < QUART_V4) {
        // Four fully independent load->store chains; ptxas batches the LDGs.
        float4 v0 = patch_val(x, tid);
        float4 v1 = patch_val(x, tid + QUART_V4);
        float4 v2 = patch_val(x, tid + 2 * QUART_V4);
        float4 v3 = patch_val(x, tid + 3 * QUART_V4);
        float4* o = reinterpret_cast<float4*>(out);
        stcs4(o + tid,                v0);
        stcs4(o + tid +     QUART_V4, v1);
        stcs4(o + tid + 2 * QUART_V4, v2);
        stcs4(o + tid + 3 * QUART_V4, v3);
    } else {
        int m = tid - QUART_V4;       // [0, MASK_N)
        int p = m % P_DIM;
        stcs1(out + (size_t)PATCH_V4 * 4 + m, (p < ACTUAL_) ? 1.0f : 0.0f);
    }
}

extern "C" void kernel_launch(void* const* d_in, const int* in_sizes, int n_in,
                              void* d_out, int out_size)
{
    const float* x   = (const float*)d_in[0];
    float*       out = (float*)d_out;

    int threads = 256;
    int blocks  = (TOTAL_T + threads - 1) / threads;   // 19,407
    to_patches_fused_kernel<<<blocks, threads>>>(x, out);
}

// round 6
// speedup vs baseline: 1.0197x; 1.0197x over previous
#include <cuda_runtime.h>
#include <stdint.h>

// Problem constants (from reference_code)
#define B_DIM    16
#define C_DIM    23
#define T_DIM    120200
#define P_DIM    1000
#define PS_DIM   200
#define STRIDE_  150
#define ACTUAL_  801           // min((T-PS)/STRIDE + 1, MAX_PATCHES)

#define BC_DIM   (B_DIM * C_DIM)                 // 368
#define V4       (PS_DIM / 4)                    // 50 float4 per patch
#define PATCH_V4 (BC_DIM * P_DIM * V4)           // 18,400,000 float4 outputs
#define MASK_N   (BC_DIM * P_DIM)                // 368,000

#define THREADS_ 512
#define UNROLL_  2
#define CHUNK_   (THREADS_ * UNROLL_)            // 1024 float4 per block
#define PATCH_BLOCKS ((PATCH_V4 + CHUNK_ - 1) / CHUNK_)   // 17,969
#define MASK_BLOCKS  ((MASK_N + THREADS_ - 1) / THREADS_) // 719

// Streaming (evict-first) stores: keep the 296MB write stream out of L2 so the
// input window (partially L2-resident across replays) stays cached.
__device__ __forceinline__ void stcs4(float4* p, float4 v) {
    asm volatile("st.global.cs.v4.f32 [%0], {%1,%2,%3,%4};"
                 :: "l"(p), "f"(v.x), "f"(v.y), "f"(v.z), "f"(v.w) : "memory");
}
__device__ __forceinline__ void stcs1(float* p, float v) {
    asm volatile("st.global.cs.f32 [%0], %1;" :: "l"(p), "f"(v) : "memory");
}

// Compute one float4 of the patches output for flat float4-index `o`.
__device__ __forceinline__ float4 patch_val(const float* __restrict__ x, int o) {
    int v    = o % V4;          // float4 index within patch [0,50)
    int rest = o / V4;
    int p    = rest % P_DIM;    // patch index [0,1000)
    int bc   = rest / P_DIM;    // fused (b,c) [0,368)

    if (p >= ACTUAL_) return make_float4(0.f, 0.f, 0.f, 0.f);

    // src offset = bc*120200 + 150*p + 4*v ; 16B-aligned iff p even.
    const float* src = x + (size_t)bc * T_DIM + p * STRIDE_ + v * 4;
    if ((p & 1) == 0) {
        return *reinterpret_cast<const float4*>(src);
    } else {
        float2 a = *reinterpret_cast<const float2*>(src);
        float2 b = *reinterpret_cast<const float2*>(src + 2);
        return make_float4(a.x, a.y, b.x, b.y);
    }
}

// Patch kernel: each block copies one CONTIGUOUS 16KB output window
// (two coalesced segments per thread, o1 = o0 + blockDim) so DRAM sees long
// same-page bursts and the overlap re-reads stay spatially local in L2.
__global__ void __launch_bounds__(THREADS_) patch_kernel(
    const float* __restrict__ x, float* __restrict__ out)
{
    int o0 = blockIdx.x * CHUNK_ + threadIdx.x;
    int o1 = o0 + THREADS_;

    // Two independent load->store chains, both in the block's local window.
    float4 v0, v1;
    bool has0 = (o0 < PATCH_V4);
    bool has1 = (o1 < PATCH_V4);
    if (has0) v0 = patch_val(x, o0);
    if (has1) v1 = patch_val(x, o1);

    float4* o = reinterpret_cast<float4*>(out);
    if (has0) stcs4(o + o0, v0);
    if (has1) stcs4(o + o1, v1);
}

// mask[bc, p] = (p < 801) ? 1 : 0
__global__ void __launch_bounds__(THREADS_) mask_kernel(float* __restrict__ out)
{
    int m = blockIdx.x * blockDim.x + threadIdx.x;
    if (m >= MASK_N) return;
    int p = m % P_DIM;
    stcs1(out + (size_t)PATCH_V4 * 4 + m, (p < ACTUAL_) ? 1.0f : 0.0f);
}

extern "C" void kernel_launch(void* const* d_in, const int* in_sizes, int n_in,
                              void* d_out, int out_size)
{
    const float* x   = (const float*)d_in[0];
    float*       out = (float*)d_out;

    patch_kernel<<<PATCH_BLOCKS, THREADS_>>>(x, out);
    mask_kernel<<<MASK_BLOCKS, THREADS_>>>(out);
}

// round 7
// speedup vs baseline: 1.0501x; 1.0298x over previous
#include <cuda_runtime.h>
#include <stdint.h>

// Problem constants (from reference_code)
#define B_DIM    16
#define C_DIM    23
#define T_DIM    120200
#define P_DIM    1000
#define PS_DIM   200
#define STRIDE_  150
#define ACTUAL_  801           // min((T-PS)/STRIDE + 1, MAX_PATCHES)

#define BC_DIM   (B_DIM * C_DIM)                 // 368
#define V4       (PS_DIM / 4)                    // 50 float4 per patch
#define PATCH_V4 (BC_DIM * P_DIM * V4)           // 18,400,000 float4 outputs
#define MASK_N   (BC_DIM * P_DIM)                // 368,000

#define THREADS_ 512
#define UNROLL_  2
#define CHUNK_   (THREADS_ * UNROLL_)            // 1024 float4 per block
#define PATCH_BLOCKS ((PATCH_V4 + CHUNK_ - 1) / CHUNK_)   // 17,969
#define MASK_BLOCKS  ((MASK_N + THREADS_ - 1) / THREADS_) // 719
#define TOTAL_BLOCKS (PATCH_BLOCKS + MASK_BLOCKS)         // 18,688

// Streaming (evict-first) stores: keep the 296MB write stream out of L2 so the
// input window (partially L2-resident across replays) stays cached.
__device__ __forceinline__ void stcs4(float4* p, float4 v) {
    asm volatile("st.global.cs.v4.f32 [%0], {%1,%2,%3,%4};"
                 :: "l"(p), "f"(v.x), "f"(v.y), "f"(v.z), "f"(v.w) : "memory");
}
__device__ __forceinline__ void stcs1(float* p, float v) {
    asm volatile("st.global.cs.f32 [%0], %1;" :: "l"(p), "f"(v) : "memory");
}

// Compute one float4 of the patches output for flat float4-index `o`.
__device__ __forceinline__ float4 patch_val(const float* __restrict__ x, int o) {
    int v    = o % V4;          // float4 index within patch [0,50)
    int rest = o / V4;
    int p    = rest % P_DIM;    // patch index [0,1000)
    int bc   = rest / P_DIM;    // fused (b,c) [0,368)

    if (p >= ACTUAL_) return make_float4(0.f, 0.f, 0.f, 0.f);

    // src offset = bc*120200 + 150*p + 4*v ; 16B-aligned iff p even.
    const float* src = x + (size_t)bc * T_DIM + p * STRIDE_ + v * 4;
    if ((p & 1) == 0) {
        return *reinterpret_cast<const float4*>(src);
    } else {
        float2 a = *reinterpret_cast<const float2*>(src);
        float2 b = *reinterpret_cast<const float2*>(src + 2);
        return make_float4(a.x, a.y, b.x, b.y);
    }
}

// Single fused launch:
//   blockIdx < PATCH_BLOCKS : block copies one contiguous 16KB output window
//     (two coalesced segments per thread, o1 = o0 + blockDim) -> long same-page
//     DRAM bursts, spatially-local L2 re-reads for the window overlap.
//   blockIdx >= PATCH_BLOCKS: mask block (runs concurrently inside the grid,
//     hidden under the patch copy instead of serialized after it).
__global__ void __launch_bounds__(THREADS_) to_patches_fused_kernel(
    const float* __restrict__ x, float* __restrict__ out)
{
    int b = blockIdx.x;

    if (b < PATCH_BLOCKS) {
        int o0 = b * CHUNK_ + threadIdx.x;
        int o1 = o0 + THREADS_;

        float4 v0, v1;
        bool has0 = (o0 < PATCH_V4);
        bool has1 = (o1 < PATCH_V4);
        if (has0) v0 = patch_val(x, o0);
        if (has1) v1 = patch_val(x, o1);

        float4* o = reinterpret_cast<float4*>(out);
        if (has0) stcs4(o + o0, v0);
        if (has1) stcs4(o + o1, v1);
    } else {
        // mask[bc, p] = (p < 801) ? 1 : 0
        int m = (b - PATCH_BLOCKS) * THREADS_ + threadIdx.x;
        if (m < MASK_N) {
            int p = m % P_DIM;
            stcs1(out + (size_t)PATCH_V4 * 4 + m, (p < ACTUAL_) ? 1.0f : 0.0f);
        }
    }
}

extern "C" void kernel_launch(void* const* d_in, const int* in_sizes, int n_in,
                              void* d_out, int out_size)
{
    const float* x   = (const float*)d_in[0];
    float*       out = (float*)d_out;

    to_patches_fused_kernel<<<TOTAL_BLOCKS, THREADS_>>>(x, out);
}